// round 5
// baseline (speedup 1.0000x reference)
#include <cuda_runtime.h>
#include <math.h>

#define NN 100000
#define EE 1000000
#define SCH 512                     // scan chunk
#define NBLK ((NN + SCH - 1) / SCH) // 196

// Scratch (device globals — no allocation allowed)
__device__ int   g_is32;
__device__ int   g_src[EE];
__device__ int   g_dst[EE];
__device__ int   g_csr[EE];
__device__ int   g_degi[NN];
__device__ int   g_off[NN + 1];
__device__ int   g_cur[NN];
__device__ int   g_part[NBLK];
__device__ int   g_carry[NBLK];
__device__ float g_dinv[NN];
__device__ __align__(16) float g_b1p[104];
__device__ __align__(16) float g_b2p[56];
__device__ __align__(16) float g_bufA[(size_t)NN * 104];
__device__ __align__(16) float g_bufB[(size_t)NN * 104];
__device__ __align__(16) float g_bufC[(size_t)NN * 56];

// ---------------- edge dtype detection ----------------
__global__ void k_detect(const long long* __restrict__ edge64, int E) {
    if (threadIdx.x == 0) g_is32 = 0;
    __syncthreads();
    int nscan = E < 4096 ? E : 4096;
    for (int i = threadIdx.x; i < nscan; i += blockDim.x) {
        long long v = edge64[i];
        if (v < 0 || v >= NN) g_is32 = 1;  // benign race
    }
}

__global__ void k_zero_deg() {
    int i = blockIdx.x * blockDim.x + threadIdx.x;
    if (i < NN) g_degi[i] = 0;
}

// convert + degree count in one edge pass
__global__ void k_convert_count(const void* __restrict__ edge, int E) {
    int e = blockIdx.x * blockDim.x + threadIdx.x;
    if (e >= E) return;
    int s, d;
    if (g_is32) {
        const int* p = (const int*)edge;
        s = p[e]; d = p[E + e];
    } else {
        const long long* p = (const long long*)edge;
        s = (int)p[e]; d = (int)p[E + e];
    }
    g_src[e] = s;
    g_dst[e] = d;
    atomicAdd(&g_degi[d], 1);
}

__global__ void k_dinv() {
    int i = blockIdx.x * blockDim.x + threadIdx.x;
    if (i < NN) g_dinv[i] = rsqrtf((float)g_degi[i] + 1.0f);  // +1 self loop
}

// ---------------- prefix scan (3 kernels) ----------------
__global__ void k_scan_part() {
    __shared__ int s[SCH];
    int t = threadIdx.x;
    int i = blockIdx.x * SCH + t;
    s[t] = (i < NN) ? g_degi[i] : 0;
    __syncthreads();
    for (int o = SCH / 2; o > 0; o >>= 1) {
        if (t < o) s[t] += s[t + o];
        __syncthreads();
    }
    if (t == 0) g_part[blockIdx.x] = s[0];
}

__global__ void k_scan_top(int E) {
    __shared__ int s[256];
    int t = threadIdx.x;
    int v = (t < NBLK) ? g_part[t] : 0;
    s[t] = v;
    __syncthreads();
    for (int o = 1; o < 256; o <<= 1) {
        int u = (t >= o) ? s[t - o] : 0;
        __syncthreads();
        s[t] += u;
        __syncthreads();
    }
    if (t < NBLK) g_carry[t] = s[t] - v;  // exclusive
    if (t == 0) g_off[NN] = E;
}

__global__ void k_scan_fin() {
    __shared__ int s[SCH];
    int t = threadIdx.x;
    int i = blockIdx.x * SCH + t;
    int v = (i < NN) ? g_degi[i] : 0;
    s[t] = v;
    __syncthreads();
    for (int o = 1; o < SCH; o <<= 1) {
        int u = (t >= o) ? s[t - o] : 0;
        __syncthreads();
        s[t] += u;
        __syncthreads();
    }
    if (i < NN) {
        int off = g_carry[blockIdx.x] + s[t] - v;  // exclusive
        g_off[i] = off;
        g_cur[i] = off;
    }
}

__global__ void k_fill(int E) {
    int e = blockIdx.x * blockDim.x + threadIdx.x;
    if (e >= E) return;
    int pos = atomicAdd(&g_cur[g_dst[e]], 1);
    g_csr[pos] = g_src[e];
}

__global__ void k_padbias(const float* __restrict__ b1, const float* __restrict__ b2) {
    int i = threadIdx.x;
    if (i < 104) g_b1p[i] = (i < 100) ? b1[i] : 0.0f;
    if (i < 56)  g_b2p[i] = (i < 50)  ? b2[i] : 0.0f;
}

// ---------------- gather aggregation ----------------
// out[i] = x[i]*dinv_i^2 + sum_{s in N(i)} x[s]*dinv_s*dinv_i ; optional relu(+bias)
template <int C, int LD, bool BR>
__global__ void k_agg(const float* __restrict__ x, float* __restrict__ out,
                      const float* __restrict__ bias) {
    int idx = blockIdx.x * blockDim.x + threadIdx.x;
    if (idx >= NN * C) return;
    int i = idx / C;
    int c = idx - i * C;
    float di = g_dinv[i];
    float s2 = di * di;
    float4 acc = *(const float4*)(x + (size_t)i * LD + c * 4);
    acc.x *= s2; acc.y *= s2; acc.z *= s2; acc.w *= s2;
    int b = g_off[i], e = g_off[i + 1];
    for (int t = b; t < e; t++) {
        int s = g_csr[t];
        float w = g_dinv[s] * di;
        float4 v = *(const float4*)(x + (size_t)s * LD + c * 4);
        acc.x = fmaf(v.x, w, acc.x);
        acc.y = fmaf(v.y, w, acc.y);
        acc.z = fmaf(v.z, w, acc.z);
        acc.w = fmaf(v.w, w, acc.w);
    }
    if (BR) {
        float4 bb = *(const float4*)(bias + c * 4);
        acc.x = fmaxf(acc.x + bb.x, 0.0f);
        acc.y = fmaxf(acc.y + bb.y, 0.0f);
        acc.z = fmaxf(acc.z + bb.z, 0.0f);
        acc.w = fmaxf(acc.w + bb.w, 0.0f);
    }
    *(float4*)(out + (size_t)i * LD + c * 4) = acc;
}

// ---------------- 8x8 register-tiled GEMM: Y = X @ W (+bias,relu) ----------------
// X: [n, LDX] (IN valid), W: [IN, OUT] row-major, Y: [n, OUTP] (OUT valid, pad 0).
// Block covers BRW rows. Threads = (BRW/8) * (OUTP/8). K chunked by KC (IN % KC == 0).
template <int IN, int LDX, int OUT, int OUTP, int KC, int BRW, bool BRELU>
__global__ void k_gemm(const float* __restrict__ X, const float* __restrict__ W,
                       const float* __restrict__ bias, float* __restrict__ Y, int n) {
    constexpr int XTS = BRW + 4;             // transposed X stride (16B-aligned, conflict-free)
    constexpr int CG = OUTP / 8;
    __shared__ float Xt[KC * XTS];
    __shared__ float Ws[KC * OUTP];
    int base = blockIdx.x * BRW;
    int rows = n - base; if (rows > BRW) rows = BRW;
    int tc = threadIdx.x % CG;
    int tr = threadIdx.x / CG;
    int r0 = tr * 8, c0 = tc * 8;

    float4 acc[8][2];
#pragma unroll
    for (int j = 0; j < 8; j++) { acc[j][0] = {0,0,0,0}; acc[j][1] = {0,0,0,0}; }

    for (int kc0 = 0; kc0 < IN; kc0 += KC) {
        // load W chunk [KC x OUTP] (pad cols >= OUT with 0)
        for (int i = threadIdx.x; i < KC * OUTP; i += blockDim.x) {
            int kk = i / OUTP, c = i - kk * OUTP;
            Ws[i] = (c < OUT) ? W[(kc0 + kk) * OUT + c] : 0.0f;
        }
        // load X chunk transposed: Xt[ck][r] (coalesced global read, conflict-free store)
        for (int i = threadIdx.x; i < BRW * KC; i += blockDim.x) {
            int r = i / KC, ck = i - r * KC;
            Xt[ck * XTS + r] = (r < rows) ? X[((size_t)base + r) * LDX + kc0 + ck] : 0.0f;
        }
        __syncthreads();
#pragma unroll 4
        for (int k = 0; k < KC; k++) {
            float4 w0 = *(const float4*)&Ws[k * OUTP + c0];
            float4 w1 = *(const float4*)&Ws[k * OUTP + c0 + 4];
            float4 xa = *(const float4*)&Xt[k * XTS + r0];
            float4 xb = *(const float4*)&Xt[k * XTS + r0 + 4];
            float xv[8] = {xa.x, xa.y, xa.z, xa.w, xb.x, xb.y, xb.z, xb.w};
#pragma unroll
            for (int j = 0; j < 8; j++) {
                acc[j][0].x = fmaf(xv[j], w0.x, acc[j][0].x);
                acc[j][0].y = fmaf(xv[j], w0.y, acc[j][0].y);
                acc[j][0].z = fmaf(xv[j], w0.z, acc[j][0].z);
                acc[j][0].w = fmaf(xv[j], w0.w, acc[j][0].w);
                acc[j][1].x = fmaf(xv[j], w1.x, acc[j][1].x);
                acc[j][1].y = fmaf(xv[j], w1.y, acc[j][1].y);
                acc[j][1].z = fmaf(xv[j], w1.z, acc[j][1].z);
                acc[j][1].w = fmaf(xv[j], w1.w, acc[j][1].w);
            }
        }
        __syncthreads();
    }

    float4 bb0 = {0,0,0,0}, bb1 = {0,0,0,0};
    if (BRELU) {
        bb0 = *(const float4*)(bias + c0);
        bb1 = *(const float4*)(bias + c0 + 4);
    }
#pragma unroll
    for (int j = 0; j < 8; j++) {
        int r = r0 + j;
        if (r < rows) {
            float4 o0 = acc[j][0], o1 = acc[j][1];
            if (BRELU) {
                o0.x = fmaxf(o0.x + bb0.x, 0.0f); o0.y = fmaxf(o0.y + bb0.y, 0.0f);
                o0.z = fmaxf(o0.z + bb0.z, 0.0f); o0.w = fmaxf(o0.w + bb0.w, 0.0f);
                o1.x = fmaxf(o1.x + bb1.x, 0.0f); o1.y = fmaxf(o1.y + bb1.y, 0.0f);
                o1.z = fmaxf(o1.z + bb1.z, 0.0f); o1.w = fmaxf(o1.w + bb1.w, 0.0f);
            }
            *(float4*)(Y + ((size_t)base + r) * OUTP + c0) = o0;
            *(float4*)(Y + ((size_t)base + r) * OUTP + c0 + 4) = o1;
        }
    }
}

// ---------------- fused epilogue: relu(agg3+b3) -> MLP 25->25->10->1 ----------------
__global__ void k_final(const float* __restrict__ agg, const float* __restrict__ b3,
                        const float* __restrict__ Wl1, const float* __restrict__ bl1,
                        const float* __restrict__ Wl2, const float* __restrict__ bl2,
                        const float* __restrict__ Wl3, const float* __restrict__ bl3,
                        float* __restrict__ out, int n) {
    __shared__ float sW1[25 * 25], sW2[25 * 10], sW3[10];
    __shared__ float sb3[25], sb1[25], sb2[10], sb3l;
    for (int i = threadIdx.x; i < 25 * 25; i += blockDim.x) sW1[i] = Wl1[i];
    for (int i = threadIdx.x; i < 25 * 10; i += blockDim.x) sW2[i] = Wl2[i];
    if (threadIdx.x < 10) sW3[threadIdx.x] = Wl3[threadIdx.x];
    if (threadIdx.x < 25) { sb3[threadIdx.x] = b3[threadIdx.x]; sb1[threadIdx.x] = bl1[threadIdx.x]; }
    if (threadIdx.x < 10) sb2[threadIdx.x] = bl2[threadIdx.x];
    if (threadIdx.x == 0) sb3l = bl3[0];
    __syncthreads();

    int i = blockIdx.x * blockDim.x + threadIdx.x;
    if (i >= n) return;

    float v[25];
#pragma unroll
    for (int f = 0; f < 25; f++)
        v[f] = fmaxf(agg[(size_t)i * 32 + f] + sb3[f], 0.0f);

    float h1[25];
#pragma unroll
    for (int c = 0; c < 25; c++) {
        float a = sb1[c];
#pragma unroll
        for (int k = 0; k < 25; k++) a = fmaf(v[k], sW1[k * 25 + c], a);
        h1[c] = fmaxf(a, 0.0f);
    }
    float h2[10];
#pragma unroll
    for (int c = 0; c < 10; c++) {
        float a = sb2[c];
#pragma unroll
        for (int k = 0; k < 25; k++) a = fmaf(h1[k], sW2[k * 10 + c], a);
        h2[c] = fmaxf(a, 0.0f);
    }
    float o = sb3l;
#pragma unroll
    for (int k = 0; k < 10; k++) o = fmaf(h2[k], sW3[k], o);
    out[i] = fmaxf(o, 0.0f);
}

// ---------------- launch ----------------
extern "C" void kernel_launch(void* const* d_in, const int* in_sizes, int n_in,
                              void* d_out, int out_size) {
    const float* x   = (const float*)d_in[0];
    const float* W1  = (const float*)d_in[1];
    const float* b1  = (const float*)d_in[2];
    const float* W2  = (const float*)d_in[3];
    const float* b2  = (const float*)d_in[4];
    const float* W3  = (const float*)d_in[5];
    const float* b3  = (const float*)d_in[6];
    const float* Wl1 = (const float*)d_in[7];
    const float* bl1 = (const float*)d_in[8];
    const float* Wl2 = (const float*)d_in[9];
    const float* bl2 = (const float*)d_in[10];
    const float* Wl3 = (const float*)d_in[11];
    const float* bl3 = (const float*)d_in[12];
    const void* edge = d_in[13];
    int E = in_sizes[13] / 2;

    float *A, *B, *C, *b1p, *b2p;
    cudaGetSymbolAddress((void**)&A, g_bufA);
    cudaGetSymbolAddress((void**)&B, g_bufB);
    cudaGetSymbolAddress((void**)&C, g_bufC);
    cudaGetSymbolAddress((void**)&b1p, g_b1p);
    cudaGetSymbolAddress((void**)&b2p, g_b2p);

    const int T = 256;
    int gN = (NN + T - 1) / T;
    int gE = (E + T - 1) / T;

    // edge normalization + CSR build (once per launch, shared by 3 layers)
    k_detect<<<1, 256>>>((const long long*)edge, E);
    k_zero_deg<<<gN, T>>>();
    k_convert_count<<<gE, T>>>(edge, E);
    k_dinv<<<gN, T>>>();
    k_scan_part<<<NBLK, SCH>>>();
    k_scan_top<<<1, 256>>>(E);
    k_scan_fin<<<NBLK, SCH>>>();
    k_fill<<<gE, T>>>(E);
    k_padbias<<<1, 128>>>(b1, b2);

    // ----- Layer 1: aggregate input (64-dim), GEMM 64->100 (+b1, relu) -----
    k_agg<16, 64, false><<<(NN * 16 + T - 1) / T, T>>>(x, A, nullptr);
    k_gemm<64, 64, 100, 104, 32, 128, true><<<(NN + 127) / 128, 16 * 13>>>(A, W1, b1p, B, NN);

    // ----- Layer 2: GEMM 100->50 raw (pad 56), aggregate w/ fused relu(+b2) -----
    k_gemm<100, 104, 50, 56, 25, 256, false><<<(NN + 255) / 256, 32 * 7>>>(B, W2, nullptr, A, NN);
    k_agg<14, 56, true><<<(NN * 14 + T - 1) / T, T>>>(A, C, b2p);

    // ----- Layer 3: GEMM 50->25 raw (pad 32), aggregate raw -----
    k_gemm<50, 56, 25, 32, 25, 256, false><<<(NN + 255) / 256, 32 * 4>>>(C, W3, nullptr, A, NN);
    k_agg<8, 32, false><<<(NN * 8 + T - 1) / T, T>>>(A, B, nullptr);

    // ----- fused: relu(agg3+b3) -> MLP 25->25->10->1 -----
    k_final<<<gN, T>>>(B, b3, Wl1, bl1, Wl2, bl2, Wl3, bl3, (float*)d_out, NN);
}

// round 6
// speedup vs baseline: 1.1662x; 1.1662x over previous
#include <cuda_runtime.h>
#include <math.h>

#define NN 100000
#define EE 1000000
#define SCH 512                     // scan chunk
#define NBLK ((NN + SCH - 1) / SCH) // 196

// Scratch (device globals — no allocation allowed)
__device__ int   g_is32;
__device__ int   g_src[EE];
__device__ int   g_dst[EE];
__device__ int   g_csr[EE];
__device__ int   g_degi[NN];
__device__ int   g_off[NN + 1];
__device__ int   g_cur[NN];
__device__ int   g_part[NBLK];
__device__ int   g_carry[NBLK];
__device__ float g_dinv[NN];
__device__ __align__(16) float g_b2p[52];
__device__ __align__(16) float g_bufA[(size_t)NN * 100];
__device__ __align__(16) float g_bufB[(size_t)NN * 100];
__device__ __align__(16) float g_bufC[(size_t)NN * 52];

// ---------------- edge dtype detection ----------------
__global__ void k_detect(const long long* __restrict__ edge64, int E) {
    if (threadIdx.x == 0) g_is32 = 0;
    __syncthreads();
    int nscan = E < 4096 ? E : 4096;
    for (int i = threadIdx.x; i < nscan; i += blockDim.x) {
        long long v = edge64[i];
        if (v < 0 || v >= NN) g_is32 = 1;  // benign race
    }
}

__global__ void k_zero_deg() {
    int i = blockIdx.x * blockDim.x + threadIdx.x;
    if (i < NN) g_degi[i] = 0;
}

// convert + degree count in one edge pass
__global__ void k_convert_count(const void* __restrict__ edge, int E) {
    int e = blockIdx.x * blockDim.x + threadIdx.x;
    if (e >= E) return;
    int s, d;
    if (g_is32) {
        const int* p = (const int*)edge;
        s = p[e]; d = p[E + e];
    } else {
        const long long* p = (const long long*)edge;
        s = (int)p[e]; d = (int)p[E + e];
    }
    g_src[e] = s;
    g_dst[e] = d;
    atomicAdd(&g_degi[d], 1);
}

__global__ void k_dinv() {
    int i = blockIdx.x * blockDim.x + threadIdx.x;
    if (i < NN) g_dinv[i] = rsqrtf((float)g_degi[i] + 1.0f);  // +1 self loop
}

// ---------------- prefix scan (3 kernels) ----------------
__global__ void k_scan_part() {
    __shared__ int s[SCH];
    int t = threadIdx.x;
    int i = blockIdx.x * SCH + t;
    s[t] = (i < NN) ? g_degi[i] : 0;
    __syncthreads();
    for (int o = SCH / 2; o > 0; o >>= 1) {
        if (t < o) s[t] += s[t + o];
        __syncthreads();
    }
    if (t == 0) g_part[blockIdx.x] = s[0];
}

__global__ void k_scan_top(int E) {
    __shared__ int s[256];
    int t = threadIdx.x;
    int v = (t < NBLK) ? g_part[t] : 0;
    s[t] = v;
    __syncthreads();
    for (int o = 1; o < 256; o <<= 1) {
        int u = (t >= o) ? s[t - o] : 0;
        __syncthreads();
        s[t] += u;
        __syncthreads();
    }
    if (t < NBLK) g_carry[t] = s[t] - v;  // exclusive
    if (t == 0) g_off[NN] = E;
}

__global__ void k_scan_fin() {
    __shared__ int s[SCH];
    int t = threadIdx.x;
    int i = blockIdx.x * SCH + t;
    int v = (i < NN) ? g_degi[i] : 0;
    s[t] = v;
    __syncthreads();
    for (int o = 1; o < SCH; o <<= 1) {
        int u = (t >= o) ? s[t - o] : 0;
        __syncthreads();
        s[t] += u;
        __syncthreads();
    }
    if (i < NN) {
        int off = g_carry[blockIdx.x] + s[t] - v;  // exclusive
        g_off[i] = off;
        g_cur[i] = off;
    }
}

__global__ void k_fill(int E) {
    int e = blockIdx.x * blockDim.x + threadIdx.x;
    if (e >= E) return;
    int pos = atomicAdd(&g_cur[g_dst[e]], 1);
    g_csr[pos] = g_src[e];
}

__global__ void k_padb2(const float* __restrict__ b2) {
    int i = threadIdx.x;
    if (i < 52) g_b2p[i] = (i < 50) ? b2[i] : 0.0f;
}

// ---------------- gather aggregation ----------------
// out[i] = x[i]*dinv_i^2 + sum_{s in N(i)} x[s]*dinv_s*dinv_i ; optional relu(+bias)
// SHFL variant: C power of 2 dividing 32; group leader loads csr/dinv, broadcasts.
template <int C, int LD, bool BR, bool SHFL>
__global__ void k_agg(const float* __restrict__ x, float* __restrict__ out,
                      const float* __restrict__ bias) {
    int idx = blockIdx.x * blockDim.x + threadIdx.x;
    if (idx >= NN * C) return;  // never triggers for SHFL configs (exact-fit grid)
    int i = idx / C;
    int c = idx - i * C;
    int lane = threadIdx.x & 31;
    unsigned gmask = SHFL ? (((C < 32 ? (1u << C) : 0u) - 1u) << ((lane / C) * C))
                          : 0xffffffffu;
    float di = g_dinv[i];
    float s2 = di * di;
    float4 acc = *(const float4*)(x + (size_t)i * LD + c * 4);
    acc.x *= s2; acc.y *= s2; acc.z *= s2; acc.w *= s2;
    int b = g_off[i], e = g_off[i + 1];
    for (int t = b; t < e; t++) {
        int s;
        float w;
        if (SHFL) {
            if (c == 0) {
                s = g_csr[t];
                w = g_dinv[s] * di;
            }
            s = __shfl_sync(gmask, s, 0, C);
            w = __shfl_sync(gmask, w, 0, C);
        } else {
            s = g_csr[t];
            w = g_dinv[s] * di;
        }
        float4 v = *(const float4*)(x + (size_t)s * LD + c * 4);
        acc.x = fmaf(v.x, w, acc.x);
        acc.y = fmaf(v.y, w, acc.y);
        acc.z = fmaf(v.z, w, acc.z);
        acc.w = fmaf(v.w, w, acc.w);
    }
    if (BR) {
        float4 bb = *(const float4*)(bias + c * 4);
        acc.x = fmaxf(acc.x + bb.x, 0.0f);
        acc.y = fmaxf(acc.y + bb.y, 0.0f);
        acc.z = fmaxf(acc.z + bb.z, 0.0f);
        acc.w = fmaxf(acc.w + bb.w, 0.0f);
    }
    *(float4*)(out + (size_t)i * LD + c * 4) = acc;
}

// ---------------- register-tiled GEMM (R4 4x4 config): Y = X @ W (+bias,relu) ----------------
// X: [n, LDX] (IN valid), W: [IN, OUT] row-major, Y: [n, OUTP] (OUT valid, pad 0)
// Block: 64 rows. Threads: 16 rowgroups x (OUTP/4) colgroups. Thread tile 4x4.
template <int IN, int LDX, int OUT, int OUTP, bool BR>
__global__ void k_gemm(const float* __restrict__ X, const float* __restrict__ W,
                       const float* __restrict__ bias, float* __restrict__ Y, int n) {
    constexpr int XS = IN + 1;       // padded stride (bank-conflict free)
    constexpr int CG = OUTP / 4;
    __shared__ float Xs[64 * XS];
    __shared__ float Ws[IN * OUTP];
    int base = blockIdx.x * 64;
    int rows = n - base; if (rows > 64) rows = 64;
    for (int i = threadIdx.x; i < IN * OUTP; i += blockDim.x) {
        int r = i / OUTP, c = i - r * OUTP;
        Ws[i] = (c < OUT) ? W[r * OUT + c] : 0.0f;
    }
    for (int i = threadIdx.x; i < 64 * IN; i += blockDim.x) {
        int r = i / IN, c = i - r * IN;
        Xs[r * XS + c] = (r < rows) ? X[((size_t)base + r) * LDX + c] : 0.0f;
    }
    __syncthreads();
    int tc = threadIdx.x % CG;
    int tr = threadIdx.x / CG;
    int r0 = tr * 4;
    float4 acc0 = {0,0,0,0}, acc1 = {0,0,0,0}, acc2 = {0,0,0,0}, acc3 = {0,0,0,0};
#pragma unroll 2
    for (int k = 0; k < IN; k++) {
        float4 w = *(const float4*)&Ws[k * OUTP + tc * 4];
        float x0 = Xs[(r0 + 0) * XS + k];
        float x1 = Xs[(r0 + 1) * XS + k];
        float x2 = Xs[(r0 + 2) * XS + k];
        float x3 = Xs[(r0 + 3) * XS + k];
        acc0.x = fmaf(x0, w.x, acc0.x); acc0.y = fmaf(x0, w.y, acc0.y);
        acc0.z = fmaf(x0, w.z, acc0.z); acc0.w = fmaf(x0, w.w, acc0.w);
        acc1.x = fmaf(x1, w.x, acc1.x); acc1.y = fmaf(x1, w.y, acc1.y);
        acc1.z = fmaf(x1, w.z, acc1.z); acc1.w = fmaf(x1, w.w, acc1.w);
        acc2.x = fmaf(x2, w.x, acc2.x); acc2.y = fmaf(x2, w.y, acc2.y);
        acc2.z = fmaf(x2, w.z, acc2.z); acc2.w = fmaf(x2, w.w, acc2.w);
        acc3.x = fmaf(x3, w.x, acc3.x); acc3.y = fmaf(x3, w.y, acc3.y);
        acc3.z = fmaf(x3, w.z, acc3.z); acc3.w = fmaf(x3, w.w, acc3.w);
    }
    float4 accs[4] = {acc0, acc1, acc2, acc3};
    float4 bb = {0,0,0,0};
    if (BR) bb = *(const float4*)(bias + tc * 4);
#pragma unroll
    for (int j = 0; j < 4; j++) {
        int r = r0 + j;
        if (r < rows) {
            float4 o = accs[j];
            if (BR) {
                o.x = fmaxf(o.x + bb.x, 0.0f); o.y = fmaxf(o.y + bb.y, 0.0f);
                o.z = fmaxf(o.z + bb.z, 0.0f); o.w = fmaxf(o.w + bb.w, 0.0f);
            }
            *(float4*)(Y + ((size_t)base + r) * OUTP + tc * 4) = o;
        }
    }
}

// ---------------- fused epilogue: relu(agg3+b3) -> MLP 25->25->10->1 ----------------
__global__ void k_final(const float* __restrict__ agg, const float* __restrict__ b3,
                        const float* __restrict__ Wl1, const float* __restrict__ bl1,
                        const float* __restrict__ Wl2, const float* __restrict__ bl2,
                        const float* __restrict__ Wl3, const float* __restrict__ bl3,
                        float* __restrict__ out, int n) {
    __shared__ float sW1[25 * 25], sW2[25 * 10], sW3[10];
    __shared__ float sb3[25], sb1[25], sb2[10], sb3l;
    for (int i = threadIdx.x; i < 25 * 25; i += blockDim.x) sW1[i] = Wl1[i];
    for (int i = threadIdx.x; i < 25 * 10; i += blockDim.x) sW2[i] = Wl2[i];
    if (threadIdx.x < 10) sW3[threadIdx.x] = Wl3[threadIdx.x];
    if (threadIdx.x < 25) { sb3[threadIdx.x] = b3[threadIdx.x]; sb1[threadIdx.x] = bl1[threadIdx.x]; }
    if (threadIdx.x < 10) sb2[threadIdx.x] = bl2[threadIdx.x];
    if (threadIdx.x == 0) sb3l = bl3[0];
    __syncthreads();

    int i = blockIdx.x * blockDim.x + threadIdx.x;
    if (i >= n) return;

    float v[25];
#pragma unroll
    for (int f = 0; f < 25; f++)
        v[f] = fmaxf(agg[(size_t)i * 32 + f] + sb3[f], 0.0f);

    float h1[25];
#pragma unroll
    for (int c = 0; c < 25; c++) {
        float a = sb1[c];
#pragma unroll
        for (int k = 0; k < 25; k++) a = fmaf(v[k], sW1[k * 25 + c], a);
        h1[c] = fmaxf(a, 0.0f);
    }
    float h2[10];
#pragma unroll
    for (int c = 0; c < 10; c++) {
        float a = sb2[c];
#pragma unroll
        for (int k = 0; k < 25; k++) a = fmaf(h1[k], sW2[k * 10 + c], a);
        h2[c] = fmaxf(a, 0.0f);
    }
    float o = sb3l;
#pragma unroll
    for (int k = 0; k < 10; k++) o = fmaf(h2[k], sW3[k], o);
    out[i] = fmaxf(o, 0.0f);
}

// ---------------- launch ----------------
extern "C" void kernel_launch(void* const* d_in, const int* in_sizes, int n_in,
                              void* d_out, int out_size) {
    const float* x   = (const float*)d_in[0];
    const float* W1  = (const float*)d_in[1];
    const float* b1  = (const float*)d_in[2];
    const float* W2  = (const float*)d_in[3];
    const float* b2  = (const float*)d_in[4];
    const float* W3  = (const float*)d_in[5];
    const float* b3  = (const float*)d_in[6];
    const float* Wl1 = (const float*)d_in[7];
    const float* bl1 = (const float*)d_in[8];
    const float* Wl2 = (const float*)d_in[9];
    const float* bl2 = (const float*)d_in[10];
    const float* Wl3 = (const float*)d_in[11];
    const float* bl3 = (const float*)d_in[12];
    const void* edge = d_in[13];
    int E = in_sizes[13] / 2;

    float *A, *B, *C, *b2p;
    cudaGetSymbolAddress((void**)&A, g_bufA);
    cudaGetSymbolAddress((void**)&B, g_bufB);
    cudaGetSymbolAddress((void**)&C, g_bufC);
    cudaGetSymbolAddress((void**)&b2p, g_b2p);

    const int T = 256;
    int gN = (NN + T - 1) / T;
    int gE = (E + T - 1) / T;

    // edge normalization + CSR build (once per launch, shared by 3 layers)
    k_detect<<<1, 256>>>((const long long*)edge, E);
    k_zero_deg<<<gN, T>>>();
    k_convert_count<<<gE, T>>>(edge, E);
    k_dinv<<<gN, T>>>();
    k_scan_part<<<NBLK, SCH>>>();
    k_scan_top<<<1, 256>>>(E);
    k_scan_fin<<<NBLK, SCH>>>();
    k_fill<<<gE, T>>>(E);
    k_padb2<<<1, 64>>>(b2);

    int gemmG = (NN + 63) / 64;

    // ----- Layer 1: aggregate input (64-dim, shfl C=16), GEMM 64->100 (+b1, relu) -----
    k_agg<16, 64, false, true><<<NN * 16 / T, T>>>(x, A, nullptr);
    k_gemm<64, 64, 100, 100, true><<<gemmG, 16 * 25>>>(A, W1, b1, B, NN);

    // ----- Layer 2: GEMM 100->50 raw (pad 52), aggregate w/ fused relu(+b2) -----
    k_gemm<100, 100, 50, 52, false><<<gemmG, 16 * 13>>>(B, W2, nullptr, A, NN);
    k_agg<13, 52, true, false><<<(NN * 13 + T - 1) / T, T>>>(A, C, b2p);

    // ----- Layer 3: GEMM 50->25 raw (pad 32), aggregate raw (shfl C=8) -----
    k_gemm<50, 52, 25, 32, false><<<gemmG, 16 * 8>>>(C, W3, nullptr, A, NN);
    k_agg<8, 32, false, true><<<NN * 8 / T, T>>>(A, B, nullptr);

    // ----- fused: relu(agg3+b3) -> MLP 25->25->10->1 -----
    k_final<<<gN, T>>>(B, b3, Wl1, bl1, Wl2, bl2, Wl3, bl3, (float*)d_out, NN);
}

// round 7
// speedup vs baseline: 1.3686x; 1.1736x over previous
#include <cuda_runtime.h>
#include <cuda_fp16.h>
#include <math.h>

#define NN 100000
#define EE 1000000
#define SCH 512                     // scan chunk
#define NBLK ((NN + SCH - 1) / SCH) // 196

// Scratch (device globals — no allocation allowed)
__device__ int   g_is32;
__device__ int   g_src[EE];
__device__ int   g_dst[EE];
__device__ int   g_csr[EE];
__device__ int   g_degi[NN];
__device__ int   g_off[NN + 1];
__device__ int   g_cur[NN];
__device__ int   g_part[NBLK];
__device__ int   g_carry[NBLK];
__device__ float g_dinv[NN];
__device__ __align__(16) float  g_b2p[56];
__device__ __align__(16) __half g_hbuf[(size_t)NN * 64];   // half payload buffer (reused)
__device__ __align__(16) float  g_bufA[(size_t)NN * 100];
__device__ __align__(16) float  g_bufB[(size_t)NN * 100];
__device__ __align__(16) float  g_bufC[(size_t)NN * 56];

// ---------------- edge dtype detection ----------------
__global__ void k_detect(const long long* __restrict__ edge64, int E) {
    if (threadIdx.x == 0) g_is32 = 0;
    __syncthreads();
    int nscan = E < 4096 ? E : 4096;
    for (int i = threadIdx.x; i < nscan; i += blockDim.x) {
        long long v = edge64[i];
        if (v < 0 || v >= NN) g_is32 = 1;  // benign race
    }
}

__global__ void k_zero_deg() {
    int i = blockIdx.x * blockDim.x + threadIdx.x;
    if (i < NN) g_degi[i] = 0;
}

// convert + degree count in one edge pass
__global__ void k_convert_count(const void* __restrict__ edge, int E) {
    int e = blockIdx.x * blockDim.x + threadIdx.x;
    if (e >= E) return;
    int s, d;
    if (g_is32) {
        const int* p = (const int*)edge;
        s = p[e]; d = p[E + e];
    } else {
        const long long* p = (const long long*)edge;
        s = (int)p[e]; d = (int)p[E + e];
    }
    g_src[e] = s;
    g_dst[e] = d;
    atomicAdd(&g_degi[d], 1);
}

__global__ void k_dinv() {
    int i = blockIdx.x * blockDim.x + threadIdx.x;
    if (i < NN) g_dinv[i] = rsqrtf((float)g_degi[i] + 1.0f);  // +1 self loop
}

// ---------------- prefix scan (3 kernels) ----------------
__global__ void k_scan_part() {
    __shared__ int s[SCH];
    int t = threadIdx.x;
    int i = blockIdx.x * SCH + t;
    s[t] = (i < NN) ? g_degi[i] : 0;
    __syncthreads();
    for (int o = SCH / 2; o > 0; o >>= 1) {
        if (t < o) s[t] += s[t + o];
        __syncthreads();
    }
    if (t == 0) g_part[blockIdx.x] = s[0];
}

__global__ void k_scan_top(int E) {
    __shared__ int s[256];
    int t = threadIdx.x;
    int v = (t < NBLK) ? g_part[t] : 0;
    s[t] = v;
    __syncthreads();
    for (int o = 1; o < 256; o <<= 1) {
        int u = (t >= o) ? s[t - o] : 0;
        __syncthreads();
        s[t] += u;
        __syncthreads();
    }
    if (t < NBLK) g_carry[t] = s[t] - v;  // exclusive
    if (t == 0) g_off[NN] = E;
}

__global__ void k_scan_fin() {
    __shared__ int s[SCH];
    int t = threadIdx.x;
    int i = blockIdx.x * SCH + t;
    int v = (i < NN) ? g_degi[i] : 0;
    s[t] = v;
    __syncthreads();
    for (int o = 1; o < SCH; o <<= 1) {
        int u = (t >= o) ? s[t - o] : 0;
        __syncthreads();
        s[t] += u;
        __syncthreads();
    }
    if (i < NN) {
        int off = g_carry[blockIdx.x] + s[t] - v;  // exclusive
        g_off[i] = off;
        g_cur[i] = off;
    }
}

__global__ void k_fill(int E) {
    int e = blockIdx.x * blockDim.x + threadIdx.x;
    if (e >= E) return;
    int pos = atomicAdd(&g_cur[g_dst[e]], 1);
    g_csr[pos] = g_src[e];
}

__global__ void k_padb2(const float* __restrict__ b2) {
    int i = threadIdx.x;
    if (i < 56) g_b2p[i] = (i < 50) ? b2[i] : 0.0f;
}

// ---------------- x (fp32, stride 64) -> half copy ----------------
__global__ void k_x2h(const float* __restrict__ x, __half* __restrict__ xh) {
    int idx = blockIdx.x * blockDim.x + threadIdx.x;  // NN*8, 8 floats each
    if (idx >= NN * 8) return;
    float4 a = *(const float4*)(x + (size_t)idx * 8);
    float4 b = *(const float4*)(x + (size_t)idx * 8 + 4);
    __half2 h[4];
    h[0] = __float22half2_rn(make_float2(a.x, a.y));
    h[1] = __float22half2_rn(make_float2(a.z, a.w));
    h[2] = __float22half2_rn(make_float2(b.x, b.y));
    h[3] = __float22half2_rn(make_float2(b.z, b.w));
    *(uint4*)(xh + (size_t)idx * 8) = *(uint4*)h;
}

// ---------------- gather aggregation (half payload, fp32 accum/out) ----------------
// out[i] = xh[i]*dinv_i^2 + sum_{s in N(i)} xh[s]*dinv_s*dinv_i ; optional relu(+bias)
// Each thread handles 8 features (one 16B half8 load per edge).
template <int C, int LD, bool BR>
__global__ void k_aggh(const __half* __restrict__ xh, float* __restrict__ out,
                       const float* __restrict__ bias) {
    int idx = blockIdx.x * blockDim.x + threadIdx.x;
    if (idx >= NN * C) return;
    int i = idx / C;
    int c = idx - i * C;
    float di = g_dinv[i];
    float s2 = di * di;
    float acc[8];
    {
        uint4 raw = *(const uint4*)(xh + (size_t)i * LD + c * 8);
        const __half2* hp = (const __half2*)&raw;
#pragma unroll
        for (int j = 0; j < 4; j++) {
            float2 f = __half22float2(hp[j]);
            acc[2 * j]     = f.x * s2;
            acc[2 * j + 1] = f.y * s2;
        }
    }
    int b = g_off[i], e = g_off[i + 1];
    for (int t = b; t < e; t++) {
        int s = g_csr[t];
        float w = g_dinv[s] * di;
        uint4 raw = *(const uint4*)(xh + (size_t)s * LD + c * 8);
        const __half2* hp = (const __half2*)&raw;
#pragma unroll
        for (int j = 0; j < 4; j++) {
            float2 f = __half22float2(hp[j]);
            acc[2 * j]     = fmaf(f.x, w, acc[2 * j]);
            acc[2 * j + 1] = fmaf(f.y, w, acc[2 * j + 1]);
        }
    }
    if (BR) {
#pragma unroll
        for (int j = 0; j < 8; j++)
            acc[j] = fmaxf(acc[j] + bias[c * 8 + j], 0.0f);
    }
    *(float4*)(out + (size_t)i * LD + c * 8)     = make_float4(acc[0], acc[1], acc[2], acc[3]);
    *(float4*)(out + (size_t)i * LD + c * 8 + 4) = make_float4(acc[4], acc[5], acc[6], acc[7]);
}

// ---------------- register-tiled GEMM (R4 4x4): Y = X @ W (+bias,relu | half out) ----------------
// X: [n, LDX] (IN valid), W: [IN, OUT] row-major.
// HOUT=false: Y fp32 [n, OUTP] (+bias,relu if BR). HOUT=true: Yh half [n, OUTP], raw.
template <int IN, int LDX, int OUT, int OUTP, bool BR, bool HOUT>
__global__ void k_gemm(const float* __restrict__ X, const float* __restrict__ W,
                       const float* __restrict__ bias, float* __restrict__ Y,
                       __half* __restrict__ Yh, int n) {
    constexpr int XS = IN + 1;       // padded stride (bank-conflict free)
    constexpr int CG = OUTP / 4;
    __shared__ float Xs[64 * XS];
    __shared__ float Ws[IN * OUTP];
    int base = blockIdx.x * 64;
    int rows = n - base; if (rows > 64) rows = 64;
    for (int i = threadIdx.x; i < IN * OUTP; i += blockDim.x) {
        int r = i / OUTP, c = i - r * OUTP;
        Ws[i] = (c < OUT) ? W[r * OUT + c] : 0.0f;
    }
    for (int i = threadIdx.x; i < 64 * IN; i += blockDim.x) {
        int r = i / IN, c = i - r * IN;
        Xs[r * XS + c] = (r < rows) ? X[((size_t)base + r) * LDX + c] : 0.0f;
    }
    __syncthreads();
    int tc = threadIdx.x % CG;
    int tr = threadIdx.x / CG;
    int r0 = tr * 4;
    float4 acc0 = {0,0,0,0}, acc1 = {0,0,0,0}, acc2 = {0,0,0,0}, acc3 = {0,0,0,0};
#pragma unroll 2
    for (int k = 0; k < IN; k++) {
        float4 w = *(const float4*)&Ws[k * OUTP + tc * 4];
        float x0 = Xs[(r0 + 0) * XS + k];
        float x1 = Xs[(r0 + 1) * XS + k];
        float x2 = Xs[(r0 + 2) * XS + k];
        float x3 = Xs[(r0 + 3) * XS + k];
        acc0.x = fmaf(x0, w.x, acc0.x); acc0.y = fmaf(x0, w.y, acc0.y);
        acc0.z = fmaf(x0, w.z, acc0.z); acc0.w = fmaf(x0, w.w, acc0.w);
        acc1.x = fmaf(x1, w.x, acc1.x); acc1.y = fmaf(x1, w.y, acc1.y);
        acc1.z = fmaf(x1, w.z, acc1.z); acc1.w = fmaf(x1, w.w, acc1.w);
        acc2.x = fmaf(x2, w.x, acc2.x); acc2.y = fmaf(x2, w.y, acc2.y);
        acc2.z = fmaf(x2, w.z, acc2.z); acc2.w = fmaf(x2, w.w, acc2.w);
        acc3.x = fmaf(x3, w.x, acc3.x); acc3.y = fmaf(x3, w.y, acc3.y);
        acc3.z = fmaf(x3, w.z, acc3.z); acc3.w = fmaf(x3, w.w, acc3.w);
    }
    float4 accs[4] = {acc0, acc1, acc2, acc3};
    float4 bb = {0,0,0,0};
    if (BR) bb = *(const float4*)(bias + tc * 4);
#pragma unroll
    for (int j = 0; j < 4; j++) {
        int r = r0 + j;
        if (r < rows) {
            float4 o = accs[j];
            if (HOUT) {
                __half2 h01 = __float22half2_rn(make_float2(o.x, o.y));
                __half2 h23 = __float22half2_rn(make_float2(o.z, o.w));
                uint2 pk = {*(unsigned*)&h01, *(unsigned*)&h23};
                *(uint2*)(Yh + ((size_t)base + r) * OUTP + tc * 4) = pk;
            } else {
                if (BR) {
                    o.x = fmaxf(o.x + bb.x, 0.0f); o.y = fmaxf(o.y + bb.y, 0.0f);
                    o.z = fmaxf(o.z + bb.z, 0.0f); o.w = fmaxf(o.w + bb.w, 0.0f);
                }
                *(float4*)(Y + ((size_t)base + r) * OUTP + tc * 4) = o;
            }
        }
    }
}

// ---------------- fused epilogue: relu(agg3+b3) -> MLP 25->25->10->1 ----------------
__global__ void k_final(const float* __restrict__ agg, const float* __restrict__ b3,
                        const float* __restrict__ Wl1, const float* __restrict__ bl1,
                        const float* __restrict__ Wl2, const float* __restrict__ bl2,
                        const float* __restrict__ Wl3, const float* __restrict__ bl3,
                        float* __restrict__ out, int n) {
    __shared__ float sW1[25 * 25], sW2[25 * 10], sW3[10];
    __shared__ float sb3[25], sb1[25], sb2[10], sb3l;
    for (int i = threadIdx.x; i < 25 * 25; i += blockDim.x) sW1[i] = Wl1[i];
    for (int i = threadIdx.x; i < 25 * 10; i += blockDim.x) sW2[i] = Wl2[i];
    if (threadIdx.x < 10) sW3[threadIdx.x] = Wl3[threadIdx.x];
    if (threadIdx.x < 25) { sb3[threadIdx.x] = b3[threadIdx.x]; sb1[threadIdx.x] = bl1[threadIdx.x]; }
    if (threadIdx.x < 10) sb2[threadIdx.x] = bl2[threadIdx.x];
    if (threadIdx.x == 0) sb3l = bl3[0];
    __syncthreads();

    int i = blockIdx.x * blockDim.x + threadIdx.x;
    if (i >= n) return;

    float v[25];
#pragma unroll
    for (int f = 0; f < 25; f++)
        v[f] = fmaxf(agg[(size_t)i * 32 + f] + sb3[f], 0.0f);

    float h1[25];
#pragma unroll
    for (int c = 0; c < 25; c++) {
        float a = sb1[c];
#pragma unroll
        for (int k = 0; k < 25; k++) a = fmaf(v[k], sW1[k * 25 + c], a);
        h1[c] = fmaxf(a, 0.0f);
    }
    float h2[10];
#pragma unroll
    for (int c = 0; c < 10; c++) {
        float a = sb2[c];
#pragma unroll
        for (int k = 0; k < 25; k++) a = fmaf(h1[k], sW2[k * 10 + c], a);
        h2[c] = fmaxf(a, 0.0f);
    }
    float o = sb3l;
#pragma unroll
    for (int k = 0; k < 10; k++) o = fmaf(h2[k], sW3[k], o);
    out[i] = fmaxf(o, 0.0f);
}

// ---------------- launch ----------------
extern "C" void kernel_launch(void* const* d_in, const int* in_sizes, int n_in,
                              void* d_out, int out_size) {
    const float* x   = (const float*)d_in[0];
    const float* W1  = (const float*)d_in[1];
    const float* b1  = (const float*)d_in[2];
    const float* W2  = (const float*)d_in[3];
    const float* b2  = (const float*)d_in[4];
    const float* W3  = (const float*)d_in[5];
    const float* b3  = (const float*)d_in[6];
    const float* Wl1 = (const float*)d_in[7];
    const float* bl1 = (const float*)d_in[8];
    const float* Wl2 = (const float*)d_in[9];
    const float* bl2 = (const float*)d_in[10];
    const float* Wl3 = (const float*)d_in[11];
    const float* bl3 = (const float*)d_in[12];
    const void* edge = d_in[13];
    int E = in_sizes[13] / 2;

    float *A, *B, *C, *b2p;
    __half *H;
    cudaGetSymbolAddress((void**)&A, g_bufA);
    cudaGetSymbolAddress((void**)&B, g_bufB);
    cudaGetSymbolAddress((void**)&C, g_bufC);
    cudaGetSymbolAddress((void**)&b2p, g_b2p);
    cudaGetSymbolAddress((void**)&H, g_hbuf);

    const int T = 256;
    int gN = (NN + T - 1) / T;
    int gE = (E + T - 1) / T;

    // edge normalization + CSR build (once per launch, shared by 3 layers)
    k_detect<<<1, 256>>>((const long long*)edge, E);
    k_zero_deg<<<gN, T>>>();
    k_convert_count<<<gE, T>>>(edge, E);
    k_dinv<<<gN, T>>>();
    k_scan_part<<<NBLK, SCH>>>();
    k_scan_top<<<1, 256>>>(E);
    k_scan_fin<<<NBLK, SCH>>>();
    k_fill<<<gE, T>>>(E);
    k_padb2<<<1, 64>>>(b2);

    int gemmG = (NN + 63) / 64;

    // ----- Layer 1: x->half, aggregate (64-dim), GEMM 64->100 (+b1, relu) -----
    k_x2h<<<(NN * 8 + T - 1) / T, T>>>(x, H);
    k_aggh<8, 64, false><<<NN * 8 / T, T>>>(H, A, nullptr);
    k_gemm<64, 64, 100, 100, true, false><<<gemmG, 16 * 25>>>(A, W1, b1, B, nullptr, NN);

    // ----- Layer 2: GEMM 100->50 raw half (pad 56), aggregate w/ fused relu(+b2) -----
    k_gemm<100, 100, 50, 56, false, true><<<gemmG, 16 * 14>>>(B, W2, nullptr, nullptr, H, NN);
    k_aggh<7, 56, true><<<(NN * 7 + T - 1) / T, T>>>(H, C, b2p);

    // ----- Layer 3: GEMM 50->25 raw half (pad 32), aggregate raw -----
    k_gemm<50, 56, 25, 32, false, true><<<gemmG, 16 * 8>>>(C, W3, nullptr, nullptr, H, NN);
    k_aggh<4, 32, false><<<NN * 4 / T, T>>>(H, B, nullptr);

    // ----- fused: relu(agg3+b3) -> MLP 25->25->10->1 -----
    k_final<<<gN, T>>>(B, b3, Wl1, bl1, Wl2, bl2, Wl3, bl3, (float*)d_out, NN);
}

// round 8
// speedup vs baseline: 1.7681x; 1.2919x over previous
#include <cuda_runtime.h>
#include <cuda_fp16.h>
#include <mma.h>
#include <math.h>

using namespace nvcuda;

#define NN 100000
#define EE 1000000
#define SCH 512                     // scan chunk
#define NBLK ((NN + SCH - 1) / SCH) // 196

// Scratch (device globals — no allocation allowed)
__device__ int   g_is32;
__device__ int   g_src[EE];
__device__ int   g_dst[EE];
__device__ int   g_csr[EE];
__device__ int   g_degi[NN];
__device__ int   g_off[NN + 1];
__device__ int   g_cur[NN];
__device__ int   g_part[NBLK];
__device__ int   g_carry[NBLK];
__device__ float g_dinv[NN];
__device__ __align__(16) float  g_b1p[112];
__device__ __align__(16) float  g_b2p[64];
__device__ __align__(16) __half g_w1h[64 * 112];
__device__ __align__(16) __half g_w2h[112 * 64];
__device__ __align__(16) __half g_w3h[64 * 32];
__device__ __align__(16) __half g_hx[(size_t)NN * 64];
__device__ __align__(16) __half g_h1[(size_t)NN * 64];
__device__ __align__(16) __half g_h2[(size_t)NN * 112];
__device__ __align__(16) float  g_fout[(size_t)NN * 32];

// ---------------- edge dtype detection ----------------
__global__ void k_detect(const long long* __restrict__ edge64, int E) {
    if (threadIdx.x == 0) g_is32 = 0;
    __syncthreads();
    int nscan = E < 4096 ? E : 4096;
    for (int i = threadIdx.x; i < nscan; i += blockDim.x) {
        long long v = edge64[i];
        if (v < 0 || v >= NN) g_is32 = 1;  // benign race
    }
}

__global__ void k_zero_deg() {
    int i = blockIdx.x * blockDim.x + threadIdx.x;
    if (i < NN) g_degi[i] = 0;
}

// convert + degree count in one edge pass
__global__ void k_convert_count(const void* __restrict__ edge, int E) {
    int e = blockIdx.x * blockDim.x + threadIdx.x;
    if (e >= E) return;
    int s, d;
    if (g_is32) {
        const int* p = (const int*)edge;
        s = p[e]; d = p[E + e];
    } else {
        const long long* p = (const long long*)edge;
        s = (int)p[e]; d = (int)p[E + e];
    }
    g_src[e] = s;
    g_dst[e] = d;
    atomicAdd(&g_degi[d], 1);
}

__global__ void k_dinv() {
    int i = blockIdx.x * blockDim.x + threadIdx.x;
    if (i < NN) g_dinv[i] = rsqrtf((float)g_degi[i] + 1.0f);  // +1 self loop
}

// ---------------- prefix scan (3 kernels) ----------------
__global__ void k_scan_part() {
    __shared__ int s[SCH];
    int t = threadIdx.x;
    int i = blockIdx.x * SCH + t;
    s[t] = (i < NN) ? g_degi[i] : 0;
    __syncthreads();
    for (int o = SCH / 2; o > 0; o >>= 1) {
        if (t < o) s[t] += s[t + o];
        __syncthreads();
    }
    if (t == 0) g_part[blockIdx.x] = s[0];
}

__global__ void k_scan_top(int E) {
    __shared__ int s[256];
    int t = threadIdx.x;
    int v = (t < NBLK) ? g_part[t] : 0;
    s[t] = v;
    __syncthreads();
    for (int o = 1; o < 256; o <<= 1) {
        int u = (t >= o) ? s[t - o] : 0;
        __syncthreads();
        s[t] += u;
        __syncthreads();
    }
    if (t < NBLK) g_carry[t] = s[t] - v;  // exclusive
    if (t == 0) g_off[NN] = E;
}

__global__ void k_scan_fin() {
    __shared__ int s[SCH];
    int t = threadIdx.x;
    int i = blockIdx.x * SCH + t;
    int v = (i < NN) ? g_degi[i] : 0;
    s[t] = v;
    __syncthreads();
    for (int o = 1; o < SCH; o <<= 1) {
        int u = (t >= o) ? s[t - o] : 0;
        __syncthreads();
        s[t] += u;
        __syncthreads();
    }
    if (i < NN) {
        int off = g_carry[blockIdx.x] + s[t] - v;  // exclusive
        g_off[i] = off;
        g_cur[i] = off;
    }
}

__global__ void k_fill(int E) {
    int e = blockIdx.x * blockDim.x + threadIdx.x;
    if (e >= E) return;
    int pos = atomicAdd(&g_cur[g_dst[e]], 1);
    g_csr[pos] = g_src[e];
}

// ---------------- weight/bias pad+convert (once per launch) ----------------
__global__ void k_padw(const float* __restrict__ W1, const float* __restrict__ W2,
                       const float* __restrict__ W3, const float* __restrict__ b1,
                       const float* __restrict__ b2) {
    int i = blockIdx.x * blockDim.x + threadIdx.x;
    if (i < 64 * 112) {
        int r = i / 112, c = i - r * 112;
        g_w1h[i] = __float2half(c < 100 ? W1[r * 100 + c] : 0.0f);
    } else if (i < 64 * 112 + 112 * 64) {
        int j = i - 64 * 112;
        int r = j / 64, c = j - r * 64;
        g_w2h[j] = __float2half((r < 100 && c < 50) ? W2[r * 50 + c] : 0.0f);
    } else if (i < 64 * 112 + 112 * 64 + 64 * 32) {
        int j = i - 64 * 112 - 112 * 64;
        int r = j / 32, c = j - r * 32;
        g_w3h[j] = __float2half((r < 50 && c < 25) ? W3[r * 25 + c] : 0.0f);
    }
    if (i < 112) g_b1p[i] = (i < 100) ? b1[i] : 0.0f;
    if (i < 64)  g_b2p[i] = (i < 50)  ? b2[i] : 0.0f;
}

// ---------------- x (fp32, stride 64) -> half ----------------
__global__ void k_x2h(const float* __restrict__ x, __half* __restrict__ xh) {
    int idx = blockIdx.x * blockDim.x + threadIdx.x;  // NN*8 groups of 8
    if (idx >= NN * 8) return;
    float4 a = *(const float4*)(x + (size_t)idx * 8);
    float4 b = *(const float4*)(x + (size_t)idx * 8 + 4);
    __half2 h[4];
    h[0] = __float22half2_rn(make_float2(a.x, a.y));
    h[1] = __float22half2_rn(make_float2(a.z, a.w));
    h[2] = __float22half2_rn(make_float2(b.x, b.y));
    h[3] = __float22half2_rn(make_float2(b.z, b.w));
    *(uint4*)(xh + (size_t)idx * 8) = *(uint4*)h;
}

// ---------------- gather aggregation (half payload, fp32 accum) ----------------
// res[i] = xh[i]*dinv_i^2 + sum_{s in N(i)} xh[s]*dinv_s*dinv_i ; opt relu(+bias)
// Output: half (HOUT) or fp32. Thread = 8 features (one 16B load per edge).
template <int C, int LD, bool BR, bool HOUT>
__global__ void k_aggh(const __half* __restrict__ xh, float* __restrict__ out,
                       __half* __restrict__ outh, const float* __restrict__ bias) {
    int idx = blockIdx.x * blockDim.x + threadIdx.x;
    if (idx >= NN * C) return;
    int i = idx / C;
    int c = idx - i * C;
    float di = g_dinv[i];
    float s2 = di * di;
    float acc[8];
    {
        uint4 raw = *(const uint4*)(xh + (size_t)i * LD + c * 8);
        const __half2* hp = (const __half2*)&raw;
#pragma unroll
        for (int j = 0; j < 4; j++) {
            float2 f = __half22float2(hp[j]);
            acc[2 * j]     = f.x * s2;
            acc[2 * j + 1] = f.y * s2;
        }
    }
    int b = g_off[i], e = g_off[i + 1];
    for (int t = b; t < e; t++) {
        int s = g_csr[t];
        float w = g_dinv[s] * di;
        uint4 raw = *(const uint4*)(xh + (size_t)s * LD + c * 8);
        const __half2* hp = (const __half2*)&raw;
#pragma unroll
        for (int j = 0; j < 4; j++) {
            float2 f = __half22float2(hp[j]);
            acc[2 * j]     = fmaf(f.x, w, acc[2 * j]);
            acc[2 * j + 1] = fmaf(f.y, w, acc[2 * j + 1]);
        }
    }
    if (BR) {
#pragma unroll
        for (int j = 0; j < 8; j++)
            acc[j] = fmaxf(acc[j] + bias[c * 8 + j], 0.0f);
    }
    if (HOUT) {
        __half2 h[4];
#pragma unroll
        for (int j = 0; j < 4; j++)
            h[j] = __float22half2_rn(make_float2(acc[2 * j], acc[2 * j + 1]));
        *(uint4*)(outh + (size_t)i * LD + c * 8) = *(uint4*)h;
    } else {
        *(float4*)(out + (size_t)i * LD + c * 8)     = make_float4(acc[0], acc[1], acc[2], acc[3]);
        *(float4*)(out + (size_t)i * LD + c * 8 + 4) = make_float4(acc[4], acc[5], acc[6], acc[7]);
    }
}

// ---------------- wmma GEMM: Yh = [relu](Xh @ Wh [+ b]) ----------------
// Xh: half [n, KP] (zero-padded cols), Wh: half [KP, NP] (zero-padded).
// 4 warps/block, 64 rows/block; warp w owns rows [16w,16w+16), loops NP/16 tiles.
template <int KP, int NP, bool BR>
__global__ void k_gemm_wmma(const __half* __restrict__ X, const __half* __restrict__ W,
                            const float* __restrict__ bias, __half* __restrict__ Yh, int n) {
    constexpr int NT = NP / 16, KT = KP / 16;
    constexpr int SM_AB = 64 * KP * 2 + KP * NP * 2;
    constexpr int SM_O  = 64 * NP * 4;
    constexpr int SM = SM_AB > SM_O ? SM_AB : SM_O;
    __shared__ __align__(32) char sm[SM];
    __half* Xs = (__half*)sm;                       // [64, KP]
    __half* Ws = (__half*)(sm + 64 * KP * 2);       // [KP, NP]
    float*  Os = (float*)sm;                        // reused after K loop: [64, NP]

    int tid = threadIdx.x;
    int wid = tid >> 5;
    int base = blockIdx.x * 64;

    for (int i = tid; i < KP * NP / 8; i += blockDim.x)
        ((uint4*)Ws)[i] = ((const uint4*)W)[i];
    constexpr int RW = KP / 8;  // uint4 per row
    for (int i = tid; i < 64 * RW; i += blockDim.x) {
        int r = i / RW, c = i - r * RW;
        uint4 v = {0, 0, 0, 0};
        if (base + r < n) v = ((const uint4*)(X + (size_t)(base + r) * KP))[c];
        ((uint4*)Xs)[i] = v;
    }
    __syncthreads();

    wmma::fragment<wmma::accumulator, 16, 16, 16, float> cf[NT];
#pragma unroll
    for (int nt = 0; nt < NT; nt++) wmma::fill_fragment(cf[nt], 0.0f);

#pragma unroll
    for (int kt = 0; kt < KT; kt++) {
        wmma::fragment<wmma::matrix_a, 16, 16, 16, __half, wmma::row_major> af;
        wmma::load_matrix_sync(af, Xs + wid * 16 * KP + kt * 16, KP);
#pragma unroll
        for (int nt = 0; nt < NT; nt++) {
            wmma::fragment<wmma::matrix_b, 16, 16, 16, __half, wmma::row_major> bf;
            wmma::load_matrix_sync(bf, Ws + kt * 16 * NP + nt * 16, NP);
            wmma::mma_sync(cf[nt], af, bf, cf[nt]);
        }
    }
    __syncthreads();  // done with Xs/Ws; alias as Os
#pragma unroll
    for (int nt = 0; nt < NT; nt++)
        wmma::store_matrix_sync(Os + wid * 16 * NP + nt * 16, cf[nt], NP, wmma::mem_row_major);
    __syncthreads();

    constexpr int CW = NP / 4;  // float4 groups per row
    for (int i = tid; i < 64 * CW; i += blockDim.x) {
        int r = i / CW, c = i - r * CW;
        if (base + r >= n) continue;
        float4 v = ((const float4*)(Os + r * NP))[c];
        if (BR) {
            float4 bb = *(const float4*)(bias + c * 4);
            v.x = fmaxf(v.x + bb.x, 0.0f); v.y = fmaxf(v.y + bb.y, 0.0f);
            v.z = fmaxf(v.z + bb.z, 0.0f); v.w = fmaxf(v.w + bb.w, 0.0f);
        }
        __half2 h01 = __float22half2_rn(make_float2(v.x, v.y));
        __half2 h23 = __float22half2_rn(make_float2(v.z, v.w));
        uint2 pk = {*(unsigned*)&h01, *(unsigned*)&h23};
        *(uint2*)(Yh + (size_t)(base + r) * NP + c * 4) = pk;
    }
}

// ---------------- fused epilogue: relu(agg3+b3) -> MLP 25->25->10->1 ----------------
__global__ void k_final(const float* __restrict__ agg, const float* __restrict__ b3,
                        const float* __restrict__ Wl1, const float* __restrict__ bl1,
                        const float* __restrict__ Wl2, const float* __restrict__ bl2,
                        const float* __restrict__ Wl3, const float* __restrict__ bl3,
                        float* __restrict__ out, int n) {
    __shared__ float sW1[25 * 25], sW2[25 * 10], sW3[10];
    __shared__ float sb3[25], sb1[25], sb2[10], sb3l;
    for (int i = threadIdx.x; i < 25 * 25; i += blockDim.x) sW1[i] = Wl1[i];
    for (int i = threadIdx.x; i < 25 * 10; i += blockDim.x) sW2[i] = Wl2[i];
    if (threadIdx.x < 10) sW3[threadIdx.x] = Wl3[threadIdx.x];
    if (threadIdx.x < 25) { sb3[threadIdx.x] = b3[threadIdx.x]; sb1[threadIdx.x] = bl1[threadIdx.x]; }
    if (threadIdx.x < 10) sb2[threadIdx.x] = bl2[threadIdx.x];
    if (threadIdx.x == 0) sb3l = bl3[0];
    __syncthreads();

    int i = blockIdx.x * blockDim.x + threadIdx.x;
    if (i >= n) return;

    float v[25];
#pragma unroll
    for (int f = 0; f < 25; f++)
        v[f] = fmaxf(agg[(size_t)i * 32 + f] + sb3[f], 0.0f);

    float h1[25];
#pragma unroll
    for (int c = 0; c < 25; c++) {
        float a = sb1[c];
#pragma unroll
        for (int k = 0; k < 25; k++) a = fmaf(v[k], sW1[k * 25 + c], a);
        h1[c] = fmaxf(a, 0.0f);
    }
    float h2[10];
#pragma unroll
    for (int c = 0; c < 10; c++) {
        float a = sb2[c];
#pragma unroll
        for (int k = 0; k < 25; k++) a = fmaf(h1[k], sW2[k * 10 + c], a);
        h2[c] = fmaxf(a, 0.0f);
    }
    float o = sb3l;
#pragma unroll
    for (int k = 0; k < 10; k++) o = fmaf(h2[k], sW3[k], o);
    out[i] = fmaxf(o, 0.0f);
}

// ---------------- launch ----------------
extern "C" void kernel_launch(void* const* d_in, const int* in_sizes, int n_in,
                              void* d_out, int out_size) {
    const float* x   = (const float*)d_in[0];
    const float* W1  = (const float*)d_in[1];
    const float* b1  = (const float*)d_in[2];
    const float* W2  = (const float*)d_in[3];
    const float* b2  = (const float*)d_in[4];
    const float* W3  = (const float*)d_in[5];
    const float* b3  = (const float*)d_in[6];
    const float* Wl1 = (const float*)d_in[7];
    const float* bl1 = (const float*)d_in[8];
    const float* Wl2 = (const float*)d_in[9];
    const float* bl2 = (const float*)d_in[10];
    const float* Wl3 = (const float*)d_in[11];
    const float* bl3 = (const float*)d_in[12];
    const void* edge = d_in[13];
    int E = in_sizes[13] / 2;

    float *b1p, *b2p, *F;
    __half *HX, *H1, *H2, *W1H, *W2H, *W3H;
    cudaGetSymbolAddress((void**)&b1p, g_b1p);
    cudaGetSymbolAddress((void**)&b2p, g_b2p);
    cudaGetSymbolAddress((void**)&F,   g_fout);
    cudaGetSymbolAddress((void**)&HX,  g_hx);
    cudaGetSymbolAddress((void**)&H1,  g_h1);
    cudaGetSymbolAddress((void**)&H2,  g_h2);
    cudaGetSymbolAddress((void**)&W1H, g_w1h);
    cudaGetSymbolAddress((void**)&W2H, g_w2h);
    cudaGetSymbolAddress((void**)&W3H, g_w3h);

    const int T = 256;
    int gN = (NN + T - 1) / T;
    int gE = (E + T - 1) / T;

    // edge normalization + CSR build (once per launch, shared by 3 layers)
    k_detect<<<1, 256>>>((const long long*)edge, E);
    k_zero_deg<<<gN, T>>>();
    k_convert_count<<<gE, T>>>(edge, E);
    k_dinv<<<gN, T>>>();
    k_scan_part<<<NBLK, SCH>>>();
    k_scan_top<<<1, 256>>>(E);
    k_scan_fin<<<NBLK, SCH>>>();
    k_fill<<<gE, T>>>(E);
    k_padw<<<64, T>>>(W1, W2, W3, b1, b2);

    int gemmG = (NN + 63) / 64;

    // ----- Layer 1: x->half; agg (64) -> half; wmma 64->112 (+b1,relu) -> half -----
    k_x2h<<<NN * 8 / T, T>>>(x, HX);
    k_aggh<8, 64, false, true><<<NN * 8 / T, T>>>(HX, nullptr, H1, nullptr);
    k_gemm_wmma<64, 112, true><<<gemmG, 128>>>(H1, W1H, b1p, H2, NN);

    // ----- Layer 2: wmma 112->64 raw -> half; agg (64) +b2,relu -> half -----
    k_gemm_wmma<112, 64, false><<<gemmG, 128>>>(H2, W2H, nullptr, HX, NN);
    k_aggh<8, 64, true, true><<<NN * 8 / T, T>>>(HX, nullptr, H1, b2p);

    // ----- Layer 3: wmma 64->32 raw -> half; agg (32) -> fp32 -----
    k_gemm_wmma<64, 32, false><<<gemmG, 128>>>(H1, W3H, nullptr, H2, NN);
    k_aggh<4, 32, false, false><<<(NN * 4 + T - 1) / T, T>>>(H2, F, nullptr, nullptr);

    // ----- fused: relu(agg3+b3) -> MLP 25->25->10->1 -----
    k_final<<<gN, T>>>(F, b3, Wl1, bl1, Wl2, bl2, Wl3, bl3, (float*)d_out, NN);
}